// round 17
// baseline (speedup 1.0000x reference)
#include <cuda_runtime.h>
#include <cuda_bf16.h>
#include <stdint.h>

// SimplifiedMambaBlock == identity on x (scan is multiplicative-only from
// h0=0 => SSM path is exactly zero; out = residual = x). rel_err=0.0 on HW.
//
// History:
//   R8  SM copy (2x, long idx, plain st):  10.94 us
//   R12 SM copy (4x, long idx):            15.10 us (regs/occ regression)
//   R15 SM copy (2x, int idx, __stcs):     10.75 us
//   R16 CE cudaMemcpyAsync node:           10.72 us
// R16 tie vs R15 => shared memory-system bound (~6.3 TB/s combined).
//
// This round: R15 structure but PLAIN stores (no __stcs). Mechanism under
// test: stcs evict-first was forcing the dst write stream to DRAM; default
// stores let dst dirty lines persist in L2 across graph replays and be
// overwritten in place, trimming DRAM writeback. Expect 10.4-10.8.

__global__ __launch_bounds__(256) void copy_f4_kernel(
    const float4* __restrict__ src, float4* __restrict__ dst, int n4) {
    const int stride = gridDim.x * blockDim.x;
    int i = blockIdx.x * blockDim.x + threadIdx.x;
    // 2x unrolled: two independent LDG.128s in flight, then 2 STG.128s
    for (; i + stride < n4; i += 2 * stride) {
        float4 a = src[i];
        float4 b = src[i + stride];
        dst[i] = a;
        dst[i + stride] = b;
    }
    if (i < n4) {
        dst[i] = src[i];
    }
}

__global__ __launch_bounds__(256) void copy_f1_tail_kernel(
    const float* __restrict__ src, float* __restrict__ dst, int start, int n) {
    int i = start + blockIdx.x * blockDim.x + threadIdx.x;
    if (i < n) dst[i] = src[i];
}

extern "C" void kernel_launch(void* const* d_in, const int* in_sizes, int n_in,
                              void* d_out, int out_size) {
    const float* x = (const float*)d_in[0];
    float* out = (float*)d_out;

    int n = out_size;                 // 8*2048*512 = 8388608
    int n4 = n >> 2;                  // 2097152 float4s

    const int threads = 256;
    int blocks = 148 * 8;             // 1184 blocks = one full wave @occ 8
    copy_f4_kernel<<<blocks, threads>>>((const float4*)x, (float4*)out, n4);

    // Tail for element counts not divisible by 4 (not hit for this shape,
    // kept for shape-variant robustness).
    int tail_start = n4 << 2;
    if (tail_start < n) {
        int tail = n - tail_start;
        int tblocks = (tail + threads - 1) / threads;
        copy_f1_tail_kernel<<<tblocks, threads>>>(x, out, tail_start, n);
    }
}